// round 1
// baseline (speedup 1.0000x reference)
#include <cuda_runtime.h>
#include <cuda_bf16.h>
#include <math.h>

// ---------------------------------------------------------------------------
// Decoder (6-layer transformer decoder) — Round 1 fp32 baseline
// B=4, S=SE=512, D_MODEL=512, H=8, DK=DV=64, D_FF=2048, VOCAB=37000, NX=6
// ---------------------------------------------------------------------------

#define Bb_ 4
#define Ss_ 512
#define Dm_ 512
#define Hh_ 8
#define Dk_ 64
#define Ff_ 2048
#define Vv_ 37000
#define Nx_ 6
#define BS_ (Bb_*Ss_)          // 2048 tokens

// ------------------------- scratch (static device globals) -----------------
__device__ float g_x    [BS_*Dm_];                 // current activations [2048,512]
__device__ float g_tmp  [BS_*Dm_];                 // residual+sublayer (BN input)
__device__ float g_attn [BS_*Dm_];                 // attn concat out [B,S,H*dv]
__device__ float g_q    [Hh_*BS_*Dk_];             // [H][B*S][64]
__device__ float g_k    [Hh_*BS_*Dk_];
__device__ float g_v    [Hh_*BS_*Dk_];
__device__ float g_sc   [Bb_*Hh_*Ss_*Ss_];         // scores/probs [BH][512][512]
__device__ float g_ff   [BS_*Ff_];                 // FF hidden [2048,2048]
__device__ float g_mu   [Dm_];
__device__ float g_rstd [Dm_];

// ------------------------------ GEMM ---------------------------------------
// C[z] = alpha * A[z] @ B[z](^T) (+bias)(+res)(relu), batched with two-level
// offsets: ptr + (z/div)*s1 + (z%div)*s2.
#define BM 128
#define BN 128
#define BK 16

__global__ __launch_bounds__(256) void gemm_kernel(
    const float* __restrict__ A, const float* __restrict__ Bt,
    float* __restrict__ C, const float* __restrict__ bias,
    const float* __restrict__ res,
    int M, int N, int K, int lda, int ldb, int ldc,
    long long aS1, long long aS2, int aDiv,
    long long bS1, long long bS2, int bDiv,
    long long cS1, long long cS2, int cDiv,
    float alpha, int transB, int relu)
{
    const int z = blockIdx.z;
    const float* Ab = A  + (long long)(z / aDiv) * aS1 + (long long)(z % aDiv) * aS2;
    const float* Bb = Bt + (long long)(z / bDiv) * bS1 + (long long)(z % bDiv) * bS2;
    float*       Cb = C  + (long long)(z / cDiv) * cS1 + (long long)(z % cDiv) * cS2;

    __shared__ float As[BK][BM + 4];
    __shared__ float Bs[BK][BN + 4];

    const int tx = threadIdx.x, ty = threadIdx.y;
    const int tid = ty * 16 + tx;
    const int m0 = blockIdx.y * BM, n0 = blockIdx.x * BN;

    float acc[8][8];
#pragma unroll
    for (int i = 0; i < 8; i++)
#pragma unroll
        for (int j = 0; j < 8; j++) acc[i][j] = 0.f;

    for (int k0 = 0; k0 < K; k0 += BK) {
        // ---- load A tile (128 x 16), rows of A are K-contiguous
#pragma unroll
        for (int l = 0; l < 2; l++) {
            int r = (tid >> 2) + l * 64;        // 0..127
            int c = (tid & 3) * 4;              // 0..12
            int gm = m0 + r;
            float4 v = make_float4(0.f, 0.f, 0.f, 0.f);
            if (gm < M)
                v = *reinterpret_cast<const float4*>(&Ab[(long long)gm * lda + k0 + c]);
            As[c + 0][r] = v.x; As[c + 1][r] = v.y;
            As[c + 2][r] = v.z; As[c + 3][r] = v.w;
        }
        // ---- load B tile (16 x 128)
        if (!transB) {
#pragma unroll
            for (int l = 0; l < 2; l++) {
                int kr = (tid >> 5) + l * 8;        // 0..15
                int nc = (tid & 31) * 4;            // 0..124
                int gn = n0 + nc;
                float4 v = make_float4(0.f, 0.f, 0.f, 0.f);
                if (gn + 3 < N) {
                    v = *reinterpret_cast<const float4*>(&Bb[(long long)(k0 + kr) * ldb + gn]);
                } else {
                    const float* p = &Bb[(long long)(k0 + kr) * ldb];
                    if (gn + 0 < N) v.x = p[gn + 0];
                    if (gn + 1 < N) v.y = p[gn + 1];
                    if (gn + 2 < N) v.z = p[gn + 2];
                    if (gn + 3 < N) v.w = p[gn + 3];
                }
                Bs[kr][nc + 0] = v.x; Bs[kr][nc + 1] = v.y;
                Bs[kr][nc + 2] = v.z; Bs[kr][nc + 3] = v.w;
            }
        } else {
            // B is [N, K]; rows are K-contiguous
#pragma unroll
            for (int l = 0; l < 2; l++) {
                int r = (tid >> 2) + l * 64;        // n row 0..127
                int c = (tid & 3) * 4;              // k col
                int gn = n0 + r;
                float4 v = make_float4(0.f, 0.f, 0.f, 0.f);
                if (gn < N)
                    v = *reinterpret_cast<const float4*>(&Bb[(long long)gn * ldb + k0 + c]);
                Bs[c + 0][r] = v.x; Bs[c + 1][r] = v.y;
                Bs[c + 2][r] = v.z; Bs[c + 3][r] = v.w;
            }
        }
        __syncthreads();

#pragma unroll
        for (int k = 0; k < BK; k++) {
            float a[8], b[8];
            *reinterpret_cast<float4*>(&a[0]) = *reinterpret_cast<const float4*>(&As[k][ty * 8]);
            *reinterpret_cast<float4*>(&a[4]) = *reinterpret_cast<const float4*>(&As[k][ty * 8 + 4]);
            *reinterpret_cast<float4*>(&b[0]) = *reinterpret_cast<const float4*>(&Bs[k][tx * 8]);
            *reinterpret_cast<float4*>(&b[4]) = *reinterpret_cast<const float4*>(&Bs[k][tx * 8 + 4]);
#pragma unroll
            for (int i = 0; i < 8; i++)
#pragma unroll
                for (int j = 0; j < 8; j++)
                    acc[i][j] = fmaf(a[i], b[j], acc[i][j]);
        }
        __syncthreads();
    }

    // ---- epilogue
#pragma unroll
    for (int i = 0; i < 8; i++) {
        int m = m0 + ty * 8 + i;
        if (m >= M) continue;
#pragma unroll
        for (int j = 0; j < 8; j++) {
            int n = n0 + tx * 8 + j;
            if (n >= N) continue;
            float v = acc[i][j] * alpha;
            if (bias) v += bias[n];
            if (res)  v += res[(long long)m * ldc + n];
            if (relu) v = fmaxf(v, 0.f);
            Cb[(long long)m * ldc + n] = v;
        }
    }
}

// --------------------------- elementwise kernels ---------------------------
__global__ void embed_kernel(const int* __restrict__ tok,
                             const float* __restrict__ emb,
                             float* __restrict__ x)
{
    int idx = blockIdx.x * 256 + threadIdx.x;     // < 2048*512
    int t = tok[idx >> 9];
    x[idx] = emb[(long long)t * Dm_ + (idx & 511)] * 8.0f;   // sqrt(d_k)=8
}

__global__ void bn_stats_kernel(const float* __restrict__ x,
                                float* __restrict__ mu, float* __restrict__ rstd)
{
    int d = blockIdx.x * 32 + threadIdx.x;
    float s = 0.f, s2 = 0.f;
    for (int i = threadIdx.y; i < BS_; i += 8) {
        float v = x[(long long)i * Dm_ + d];
        s += v; s2 += v * v;
    }
    __shared__ float sh[8][33], sh2[8][33];
    sh[threadIdx.y][threadIdx.x] = s;
    sh2[threadIdx.y][threadIdx.x] = s2;
    __syncthreads();
    if (threadIdx.y == 0) {
#pragma unroll
        for (int r = 1; r < 8; r++) { s += sh[r][threadIdx.x]; s2 += sh2[r][threadIdx.x]; }
        float m = s * (1.f / BS_);
        float var = s2 * (1.f / BS_) - m * m;
        mu[d] = m;
        rstd[d] = rsqrtf(var + 1e-5f);
    }
}

__global__ void bn_apply_kernel(const float* __restrict__ xin, float* __restrict__ xout,
                                const float* __restrict__ mu, const float* __restrict__ rstd,
                                const float* __restrict__ gamma, const float* __restrict__ beta)
{
    int idx = blockIdx.x * 256 + threadIdx.x;     // < 2048*512
    int d = idx & 511;
    xout[idx] = (xin[idx] - mu[d]) * rstd[d] * gamma[d] + beta[d];
}

// Row softmax. If causal, query position s = row & 511, mask t > s.
__global__ void softmax_kernel(float* __restrict__ p, int T, int causal)
{
    long long row = blockIdx.x;
    float* x = p + row * (long long)T;
    int s = (int)(row & 511);
    __shared__ float red[256];

    float m = -1e30f;
    for (int t = threadIdx.x; t < T; t += 256) {
        if (causal && t > s) continue;
        m = fmaxf(m, x[t]);
    }
    red[threadIdx.x] = m; __syncthreads();
    for (int o = 128; o > 0; o >>= 1) {
        if (threadIdx.x < o) red[threadIdx.x] = fmaxf(red[threadIdx.x], red[threadIdx.x + o]);
        __syncthreads();
    }
    m = red[0]; __syncthreads();

    float sum = 0.f;
    for (int t = threadIdx.x; t < T; t += 256) {
        float e = (causal && t > s) ? 0.f : expf(x[t] - m);
        x[t] = e; sum += e;
    }
    red[threadIdx.x] = sum; __syncthreads();
    for (int o = 128; o > 0; o >>= 1) {
        if (threadIdx.x < o) red[threadIdx.x] += red[threadIdx.x + o];
        __syncthreads();
    }
    float inv = 1.f / red[0];
    for (int t = threadIdx.x; t < T; t += 256) x[t] *= inv;
}

// ------------------------------- host side ---------------------------------
static inline int cdiv(int a, int b) { return (a + b - 1) / b; }

static void gemm(const float* A, const float* B, float* C,
                 const float* bias, const float* res,
                 int M, int N, int K, int lda, int ldb, int ldc,
                 long long aS1, long long aS2, int aDiv,
                 long long bS1, long long bS2, int bDiv,
                 long long cS1, long long cS2, int cDiv,
                 int batch, float alpha, int transB, int relu)
{
    dim3 blk(16, 16);
    dim3 grd(cdiv(N, BN), cdiv(M, BM), batch);
    gemm_kernel<<<grd, blk>>>(A, B, C, bias, res, M, N, K, lda, ldb, ldc,
                              aS1, aS2, aDiv, bS1, bS2, bDiv, cS1, cS2, cDiv,
                              alpha, transB, relu);
}

extern "C" void kernel_launch(void* const* d_in, const int* in_sizes, int n_in,
                              void* d_out, int out_size)
{
    const int*   tok   = (const int*)  d_in[0];
    const float* enc   = (const float*)d_in[1];
    const float* emb   = (const float*)d_in[2];
    const float* Wq1   = (const float*)d_in[3];
    const float* Wk1   = (const float*)d_in[4];
    const float* Wv1   = (const float*)d_in[5];
    const float* Wo1   = (const float*)d_in[6];
    const float* Wq2   = (const float*)d_in[7];
    const float* Wk2   = (const float*)d_in[8];
    const float* Wv2   = (const float*)d_in[9];
    const float* Wo2   = (const float*)d_in[10];
    const float* gamma = (const float*)d_in[11];
    const float* beta  = (const float*)d_in[12];
    const float* W1    = (const float*)d_in[13];
    const float* b1    = (const float*)d_in[14];
    const float* W2    = (const float*)d_in[15];
    const float* b2    = (const float*)d_in[16];
    const float* Wout  = (const float*)d_in[17];
    const float* bout  = (const float*)d_in[18];
    float* out = (float*)d_out;

    float *x, *tmp, *attn, *q, *k, *v, *sc, *ff, *mu, *rstd;
    cudaGetSymbolAddress((void**)&x,    g_x);
    cudaGetSymbolAddress((void**)&tmp,  g_tmp);
    cudaGetSymbolAddress((void**)&attn, g_attn);
    cudaGetSymbolAddress((void**)&q,    g_q);
    cudaGetSymbolAddress((void**)&k,    g_k);
    cudaGetSymbolAddress((void**)&v,    g_v);
    cudaGetSymbolAddress((void**)&sc,   g_sc);
    cudaGetSymbolAddress((void**)&ff,   g_ff);
    cudaGetSymbolAddress((void**)&mu,   g_mu);
    cudaGetSymbolAddress((void**)&rstd, g_rstd);

    const long long HW   = (long long)Dm_ * Dk_;          // 512*64 per-head weight
    const long long QH   = (long long)BS_ * Dk_;          // per-head Q/K/V block (h stride)
    const long long QB   = (long long)Ss_ * Dk_;           // per-batch block inside head
    const long long SCZ  = (long long)Ss_ * Ss_;           // scores per (b,h)
    const float     isq  = 0.125f;                          // 1/sqrt(64)

    // ---- embedding
    embed_kernel<<<BS_ * Dm_ / 256, 256>>>(tok, emb, x);

    for (int i = 0; i < Nx_; i++) {
        const float* wq1 = Wq1 + (long long)i * Hh_ * HW;
        const float* wk1 = Wk1 + (long long)i * Hh_ * HW;
        const float* wv1 = Wv1 + (long long)i * Hh_ * HW;
        const float* wo1 = Wo1 + (long long)i * Dm_ * Dm_;
        const float* wq2 = Wq2 + (long long)i * Hh_ * HW;
        const float* wk2 = Wk2 + (long long)i * Hh_ * HW;
        const float* wv2 = Wv2 + (long long)i * Hh_ * HW;
        const float* wo2 = Wo2 + (long long)i * Dm_ * Dm_;
        const float* w1  = W1  + (long long)i * Dm_ * Ff_;
        const float* w2  = W2  + (long long)i * Ff_ * Dm_;
        const float* bb1 = b1  + (long long)i * Ff_;
        const float* bb2 = b2  + (long long)i * Dm_;

        // ================= self-attention (causal) =================
        // Q/K/V: [2048,512] @ [512,64] per head -> [H][2048][64]
        gemm(x, wq1, q, nullptr, nullptr, BS_, Dk_, Dm_, Dm_, Dk_, Dk_,
             0, 0, 1,  HW, 0, 1,  QH, 0, 1,  Hh_, 1.f, 0, 0);
        gemm(x, wk1, k, nullptr, nullptr, BS_, Dk_, Dm_, Dm_, Dk_, Dk_,
             0, 0, 1,  HW, 0, 1,  QH, 0, 1,  Hh_, 1.f, 0, 0);
        gemm(x, wv1, v, nullptr, nullptr, BS_, Dk_, Dm_, Dm_, Dk_, Dk_,
             0, 0, 1,  HW, 0, 1,  QH, 0, 1,  Hh_, 1.f, 0, 0);
        // scores[z=b*H+h] = Q[b,h] @ K[b,h]^T * isq   (Q base: b*QB + h*QH)
        gemm(q, k, sc, nullptr, nullptr, Ss_, Ss_, Dk_, Dk_, Dk_, Ss_,
             QB, QH, Hh_,  QB, QH, Hh_,  SCZ, 0, 1,  Bb_ * Hh_, isq, 1, 0);
        softmax_kernel<<<Bb_ * Hh_ * Ss_, 256>>>(sc, Ss_, 1);
        // attn_concat[b,s,h*64+e] = probs @ V
        gemm(sc, v, attn, nullptr, nullptr, Ss_, Dk_, Ss_, Ss_, Dk_, Dm_,
             SCZ, 0, 1,  QB, QH, Hh_,  (long long)Ss_ * Dm_, Dk_, Hh_,
             Bb_ * Hh_, 1.f, 0, 0);
        // out = attn @ Wo + residual(x)
        gemm(attn, wo1, tmp, nullptr, x, BS_, Dm_, Dm_, Dm_, Dm_, Dm_,
             0, 0, 1,  0, 0, 1,  0, 0, 1,  1, 1.f, 0, 0);
        bn_stats_kernel<<<Dm_ / 32, dim3(32, 8)>>>(tmp, mu, rstd);
        bn_apply_kernel<<<BS_ * Dm_ / 256, 256>>>(tmp, x, mu, rstd,
                                                  gamma + (long long)(i * 3 + 0) * Dm_,
                                                  beta  + (long long)(i * 3 + 0) * Dm_);

        // ================= cross-attention =================
        gemm(x,   wq2, q, nullptr, nullptr, BS_, Dk_, Dm_, Dm_, Dk_, Dk_,
             0, 0, 1,  HW, 0, 1,  QH, 0, 1,  Hh_, 1.f, 0, 0);
        gemm(enc, wk2, k, nullptr, nullptr, BS_, Dk_, Dm_, Dm_, Dk_, Dk_,
             0, 0, 1,  HW, 0, 1,  QH, 0, 1,  Hh_, 1.f, 0, 0);
        gemm(enc, wv2, v, nullptr, nullptr, BS_, Dk_, Dm_, Dm_, Dk_, Dk_,
             0, 0, 1,  HW, 0, 1,  QH, 0, 1,  Hh_, 1.f, 0, 0);
        gemm(q, k, sc, nullptr, nullptr, Ss_, Ss_, Dk_, Dk_, Dk_, Ss_,
             QB, QH, Hh_,  QB, QH, Hh_,  SCZ, 0, 1,  Bb_ * Hh_, isq, 1, 0);
        softmax_kernel<<<Bb_ * Hh_ * Ss_, 256>>>(sc, Ss_, 0);
        gemm(sc, v, attn, nullptr, nullptr, Ss_, Dk_, Ss_, Ss_, Dk_, Dm_,
             SCZ, 0, 1,  QB, QH, Hh_,  (long long)Ss_ * Dm_, Dk_, Hh_,
             Bb_ * Hh_, 1.f, 0, 0);
        gemm(attn, wo2, tmp, nullptr, x, BS_, Dm_, Dm_, Dm_, Dm_, Dm_,
             0, 0, 1,  0, 0, 1,  0, 0, 1,  1, 1.f, 0, 0);
        bn_stats_kernel<<<Dm_ / 32, dim3(32, 8)>>>(tmp, mu, rstd);
        bn_apply_kernel<<<BS_ * Dm_ / 256, 256>>>(tmp, x, mu, rstd,
                                                  gamma + (long long)(i * 3 + 1) * Dm_,
                                                  beta  + (long long)(i * 3 + 1) * Dm_);

        // ================= feed-forward =================
        gemm(x, w1, ff, bb1, nullptr, BS_, Ff_, Dm_, Dm_, Ff_, Ff_,
             0, 0, 1,  0, 0, 1,  0, 0, 1,  1, 1.f, 0, 1);
        gemm(ff, w2, tmp, bb2, x, BS_, Dm_, Ff_, Ff_, Dm_, Dm_,
             0, 0, 1,  0, 0, 1,  0, 0, 1,  1, 1.f, 0, 0);
        bn_stats_kernel<<<Dm_ / 32, dim3(32, 8)>>>(tmp, mu, rstd);
        bn_apply_kernel<<<BS_ * Dm_ / 256, 256>>>(tmp, x, mu, rstd,
                                                  gamma + (long long)(i * 3 + 2) * Dm_,
                                                  beta  + (long long)(i * 3 + 2) * Dm_);
    }

    // ---- output projection + vocab softmax (in-place on d_out)
    gemm(x, Wout, out, bout, nullptr, BS_, Vv_, Dm_, Dm_, Vv_, Vv_,
         0, 0, 1,  0, 0, 1,  0, 0, 1,  1, 1.f, 0, 0);
    softmax_kernel<<<BS_, 256>>>(out, Vv_, 0);

    (void)in_sizes; (void)n_in; (void)out_size;
}

// round 3
// speedup vs baseline: 2.0766x; 2.0766x over previous
#include <cuda_runtime.h>
#include <math.h>
#include <stdint.h>

// ---------------------------------------------------------------------------
// Decoder — Round 3: 3xTF32 tensor-core GEMM (fp32-accurate via hi/lo split)
// ---------------------------------------------------------------------------

#define Bb_ 4
#define Ss_ 512
#define Dm_ 512
#define Hh_ 8
#define Dk_ 64
#define Ff_ 2048
#define Vv_ 37000
#define Nx_ 6
#define BS_ 2048

// ------------------------- scratch (static device globals) -----------------
__device__ float g_x    [BS_*Dm_];
__device__ float g_tmp  [BS_*Dm_];
__device__ float g_attn [BS_*Dm_];
__device__ float g_qkv  [BS_*3*Dm_];           // [2048][1536]: Q|K|V (h-blocked)
__device__ float g_sc   [Bb_*Hh_*Ss_*Ss_];
__device__ float g_ff   [BS_*Ff_];
__device__ float g_wt   [Dm_*3*Dm_];           // packed QKV weights [512,1536]
__device__ float g_mu   [Dm_];
__device__ float g_rstd [Dm_];

// ------------------------------- helpers -----------------------------------
__device__ __forceinline__ uint32_t tf32cvt(float x) {
    uint32_t u;
    asm("cvt.rna.tf32.f32 %0, %1;" : "=r"(u) : "f"(x));
    return u;
}
__device__ __forceinline__ void tf32split(float x, uint32_t& hi, uint32_t& lo) {
    hi = tf32cvt(x);
    lo = tf32cvt(x - __uint_as_float(hi));
}

__device__ __forceinline__ void cpasync16(uint32_t dst, const void* src, int srcsize) {
    asm volatile("cp.async.cg.shared.global [%0], [%1], 16, %2;"
                 :: "r"(dst), "l"(src), "r"(srcsize));
}
__device__ __forceinline__ void cpcommit() { asm volatile("cp.async.commit_group;"); }
template <int NN> __device__ __forceinline__ void cpwait() {
    asm volatile("cp.async.wait_group %0;" :: "n"(NN));
}

__device__ __forceinline__ void mma8(float* d, const uint32_t* a, const uint32_t* b) {
    asm volatile(
        "mma.sync.aligned.m16n8k8.row.col.f32.tf32.tf32.f32 "
        "{%0,%1,%2,%3}, {%4,%5,%6,%7}, {%8,%9}, {%0,%1,%2,%3};"
        : "+f"(d[0]), "+f"(d[1]), "+f"(d[2]), "+f"(d[3])
        : "r"(a[0]), "r"(a[1]), "r"(a[2]), "r"(a[3]), "r"(b[0]), "r"(b[1]));
}

// ------------------------------ GEMM (3xTF32) -------------------------------
// C[z] = alpha * A[z] @ B[z](^T) (+bias)(+res)(relu)
// fp32-accurate: per-fragment hi/lo tf32 split, 3 MMAs per fragment pair.
// Tiles: BM=128, BN=128, BK=32. 256 threads = 8 warps (4 M x 2 N).
// flags: bit0 = relu.
#define ASZ (128*36)
#define BSZn (32*136)
#define BSZt (128*36)
#define GEMM_SMEM 73728

template <int TRANSB>
__global__ __launch_bounds__(256) void gemm_tc(
    const float* __restrict__ A, const float* __restrict__ B,
    float* __restrict__ C, const float* __restrict__ bias,
    const float* __restrict__ res,
    int M, int N, int K, int lda, int ldb, int ldc,
    long long aS1, long long aS2, int aDiv,
    long long bS1, long long bS2, int bDiv,
    long long cS1, long long cS2, int cDiv,
    float alpha, int flags)
{
    extern __shared__ float sm[];
    const int z = blockIdx.z;
    const float* Ab  = A + (long long)(z / aDiv) * aS1 + (long long)(z % aDiv) * aS2;
    const float* Bbp = B + (long long)(z / bDiv) * bS1 + (long long)(z % bDiv) * bS2;
    float*       Cb  = C + (long long)(z / cDiv) * cS1 + (long long)(z % cDiv) * cS2;

    const int BSZ = TRANSB ? BSZt : BSZn;
    float* As = sm;
    float* Bs = sm + 2 * ASZ;

    const int tid  = threadIdx.x;
    const int wid  = tid >> 5, lane = tid & 31;
    const int wm   = wid & 3,  wn   = wid >> 2;
    const int g    = lane >> 2, t   = lane & 3;
    const int m0   = blockIdx.y * 128, n0 = blockIdx.x * 128;

    const uint32_t asA = (uint32_t)__cvta_generic_to_shared(As);
    const uint32_t asB = (uint32_t)__cvta_generic_to_shared(Bs);

    float acc[2][8][4];
#pragma unroll
    for (int i = 0; i < 2; i++)
#pragma unroll
        for (int j = 0; j < 8; j++)
#pragma unroll
            for (int r = 0; r < 4; r++) acc[i][j][r] = 0.f;

    const int nIter = K >> 5;

    auto doCopy = [&](int it, int buf) {
        const int k0 = it << 5;
#pragma unroll
        for (int j = 0; j < 4; j++) {
            int i   = tid + (j << 8);
            int row = i >> 3, kq = (i & 7) << 2;
            const float* src = Ab + (long long)(m0 + row) * lda + (k0 + kq);
            cpasync16(asA + (uint32_t)((buf * ASZ + row * 36 + kq) << 2), src, 16);
        }
        if (TRANSB) {
#pragma unroll
            for (int j = 0; j < 4; j++) {
                int i   = tid + (j << 8);
                int row = i >> 3, kq = (i & 7) << 2;
                int gn  = n0 + row;
                int sz  = (gn < N) ? 16 : 0;
                const float* src = Bbp + (long long)(sz ? gn : 0) * ldb + (k0 + kq);
                cpasync16(asB + (uint32_t)((buf * BSZ + row * 36 + kq) << 2), src, sz);
            }
        } else {
#pragma unroll
            for (int j = 0; j < 4; j++) {
                int i  = tid + (j << 8);
                int kr = i >> 5, nc = (i & 31) << 2;
                int gn = n0 + nc;
                int sz = (gn < N) ? 16 : 0;
                const float* src = Bbp + (long long)(k0 + kr) * ldb + (sz ? gn : 0);
                cpasync16(asB + (uint32_t)((buf * BSZ + kr * 136 + nc) << 2), src, sz);
            }
        }
    };

    doCopy(0, 0); cpcommit();

    for (int it = 0; it < nIter; ++it) {
        const int cur = it & 1;
        if (it + 1 < nIter) { doCopy(it + 1, cur ^ 1); cpcommit(); cpwait<1>(); }
        else                { cpwait<0>(); }
        __syncthreads();

        const float* pa = As + cur * ASZ;
        const float* pb = Bs + cur * BSZ;

#pragma unroll
        for (int kk = 0; kk < 32; kk += 8) {
            uint32_t ah[2][4], al[2][4];
#pragma unroll
            for (int mt = 0; mt < 2; mt++) {
                int mr = wm * 32 + mt * 16;
                tf32split(pa[(mr + g)     * 36 + kk + t],     ah[mt][0], al[mt][0]);
                tf32split(pa[(mr + g + 8) * 36 + kk + t],     ah[mt][1], al[mt][1]);
                tf32split(pa[(mr + g)     * 36 + kk + t + 4], ah[mt][2], al[mt][2]);
                tf32split(pa[(mr + g + 8) * 36 + kk + t + 4], ah[mt][3], al[mt][3]);
            }
            uint32_t bh[8][2], bl[8][2];
#pragma unroll
            for (int nt = 0; nt < 8; nt++) {
                int nc = wn * 64 + nt * 8 + g;
                float f0, f1;
                if (TRANSB) {
                    f0 = pb[nc * 36 + kk + t];
                    f1 = pb[nc * 36 + kk + t + 4];
                } else {
                    f0 = pb[(kk + t)     * 136 + nc];
                    f1 = pb[(kk + t + 4) * 136 + nc];
                }
                tf32split(f0, bh[nt][0], bl[nt][0]);
                tf32split(f1, bh[nt][1], bl[nt][1]);
            }
#pragma unroll
            for (int mt = 0; mt < 2; mt++)
#pragma unroll
                for (int nt = 0; nt < 8; nt++) {
                    mma8(acc[mt][nt], ah[mt], bh[nt]);   // hi*hi
                    mma8(acc[mt][nt], al[mt], bh[nt]);   // lo*hi
                    mma8(acc[mt][nt], ah[mt], bl[nt]);   // hi*lo
                }
        }
        __syncthreads();
    }

    // ------------------------------ epilogue --------------------------------
    const bool relu = flags & 1;
#pragma unroll
    for (int mt = 0; mt < 2; mt++) {
#pragma unroll
        for (int hrow = 0; hrow < 2; hrow++) {
            int m = m0 + wm * 32 + mt * 16 + g + hrow * 8;
#pragma unroll
            for (int nt = 0; nt < 8; nt++) {
                int n = n0 + wn * 64 + nt * 8 + 2 * t;
                if (n < N) {
                    float v0 = acc[mt][nt][hrow * 2 + 0] * alpha;
                    float v1 = acc[mt][nt][hrow * 2 + 1] * alpha;
                    if (bias) { v0 += bias[n]; v1 += bias[n + 1]; }
                    if (res) {
                        const float* rp = res + (long long)m * ldc;
                        v0 += rp[n]; v1 += rp[n + 1];
                    }
                    if (relu) { v0 = fmaxf(v0, 0.f); v1 = fmaxf(v1, 0.f); }
                    float2 vv; vv.x = v0; vv.y = v1;
                    *(float2*)(Cb + (long long)m * ldc + n) = vv;
                }
            }
        }
    }
}

// --------------------------- elementwise kernels ---------------------------
// Pack per-layer Wq/Wk/Wv ([H,D,dk] each) into [D, 1536] (Q|K|V, h-blocked).
__global__ void pack_qkv_kernel(const float* __restrict__ Wq, const float* __restrict__ Wk,
                                const float* __restrict__ Wv, float* __restrict__ wt) {
    int idx = blockIdx.x * 256 + threadIdx.x;        // < 512*1536
    int col = idx % 1536, d = idx / 1536;
    int sel = col >> 9, c = col & 511;
    int h = c >> 6, e = c & 63;
    const float* W = (sel == 0) ? Wq : (sel == 1) ? Wk : Wv;
    wt[idx] = W[(h * Dm_ + d) * Dk_ + e];
}

__global__ void embed_kernel(const int* __restrict__ tok, const float* __restrict__ emb,
                             float* __restrict__ x) {
    int idx = blockIdx.x * 256 + threadIdx.x;        // < 2048*512
    int t = tok[idx >> 9];
    x[idx] = emb[(long long)t * Dm_ + (idx & 511)] * 8.0f;
}

__global__ void bn_stats_kernel(const float* __restrict__ x,
                                float* __restrict__ mu, float* __restrict__ rstd) {
    int d = blockIdx.x * 32 + threadIdx.x;
    float s = 0.f, s2 = 0.f;
    for (int i = threadIdx.y; i < BS_; i += 8) {
        float v = x[(long long)i * Dm_ + d];
        s += v; s2 += v * v;
    }
    __shared__ float sh[8][33], sh2[8][33];
    sh[threadIdx.y][threadIdx.x] = s;
    sh2[threadIdx.y][threadIdx.x] = s2;
    __syncthreads();
    if (threadIdx.y == 0) {
#pragma unroll
        for (int r = 1; r < 8; r++) { s += sh[r][threadIdx.x]; s2 += sh2[r][threadIdx.x]; }
        float m = s * (1.f / BS_);
        float var = s2 * (1.f / BS_) - m * m;
        mu[d] = m;
        rstd[d] = rsqrtf(var + 1e-5f);
    }
}

__global__ void bn_apply_kernel(const float* __restrict__ xin, float* __restrict__ xout,
                                const float* __restrict__ mu, const float* __restrict__ rstd,
                                const float* __restrict__ gamma, const float* __restrict__ beta) {
    int idx = blockIdx.x * 256 + threadIdx.x;
    int d = idx & 511;
    xout[idx] = (xin[idx] - mu[d]) * rstd[d] * gamma[d] + beta[d];
}

// Row softmax; causal masks t > (row & 511).
__global__ void softmax_kernel(float* __restrict__ p, int T, int causal) {
    extern __shared__ float red[];
    long long row = blockIdx.x;
    float* x = p + row * (long long)T;
    int s = (int)(row & 511);
    int nt = blockDim.x;

    float m = -1e30f;
    for (int t = threadIdx.x; t < T; t += nt) {
        if (causal && t > s) continue;
        m = fmaxf(m, x[t]);
    }
    red[threadIdx.x] = m; __syncthreads();
    for (int o = nt >> 1; o > 0; o >>= 1) {
        if ((int)threadIdx.x < o) red[threadIdx.x] = fmaxf(red[threadIdx.x], red[threadIdx.x + o]);
        __syncthreads();
    }
    m = red[0]; __syncthreads();

    float sum = 0.f;
    for (int t = threadIdx.x; t < T; t += nt) {
        float e = (causal && t > s) ? 0.f : expf(x[t] - m);
        x[t] = e; sum += e;
    }
    red[threadIdx.x] = sum; __syncthreads();
    for (int o = nt >> 1; o > 0; o >>= 1) {
        if ((int)threadIdx.x < o) red[threadIdx.x] += red[threadIdx.x + o];
        __syncthreads();
    }
    float inv = 1.f / red[0];
    for (int t = threadIdx.x; t < T; t += nt) x[t] *= inv;
}

// ------------------------------- host side ---------------------------------
static inline int cdiv(int a, int b) { return (a + b - 1) / b; }

static void gemm(const float* A, const float* B, float* C,
                 const float* bias, const float* res,
                 int M, int N, int K, int lda, int ldb, int ldc,
                 long long aS1, long long aS2, int aDiv,
                 long long bS1, long long bS2, int bDiv,
                 long long cS1, long long cS2, int cDiv,
                 int batch, float alpha, int transB, int flags)
{
    dim3 grd(cdiv(N, 128), M / 128, batch);
    if (transB)
        gemm_tc<1><<<grd, 256, GEMM_SMEM>>>(A, B, C, bias, res, M, N, K, lda, ldb, ldc,
                                            aS1, aS2, aDiv, bS1, bS2, bDiv, cS1, cS2, cDiv,
                                            alpha, flags);
    else
        gemm_tc<0><<<grd, 256, GEMM_SMEM>>>(A, B, C, bias, res, M, N, K, lda, ldb, ldc,
                                            aS1, aS2, aDiv, bS1, bS2, bDiv, cS1, cS2, cDiv,
                                            alpha, flags);
}

extern "C" void kernel_launch(void* const* d_in, const int* in_sizes, int n_in,
                              void* d_out, int out_size)
{
    const int*   tok   = (const int*)  d_in[0];
    const float* enc   = (const float*)d_in[1];
    const float* emb   = (const float*)d_in[2];
    const float* Wq1   = (const float*)d_in[3];
    const float* Wk1   = (const float*)d_in[4];
    const float* Wv1   = (const float*)d_in[5];
    const float* Wo1   = (const float*)d_in[6];
    const float* Wq2   = (const float*)d_in[7];
    const float* Wk2   = (const float*)d_in[8];
    const float* Wv2   = (const float*)d_in[9];
    const float* Wo2   = (const float*)d_in[10];
    const float* gamma = (const float*)d_in[11];
    const float* beta  = (const float*)d_in[12];
    const float* W1    = (const float*)d_in[13];
    const float* b1    = (const float*)d_in[14];
    const float* W2    = (const float*)d_in[15];
    const float* b2    = (const float*)d_in[16];
    const float* Wout  = (const float*)d_in[17];
    const float* bout  = (const float*)d_in[18];
    float* out = (float*)d_out;

    cudaFuncSetAttribute(gemm_tc<0>, cudaFuncAttributeMaxDynamicSharedMemorySize, GEMM_SMEM);
    cudaFuncSetAttribute(gemm_tc<1>, cudaFuncAttributeMaxDynamicSharedMemorySize, GEMM_SMEM);

    float *x, *tmp, *attn, *qkv, *sc, *ff, *wt, *mu, *rstd;
    cudaGetSymbolAddress((void**)&x,    g_x);
    cudaGetSymbolAddress((void**)&tmp,  g_tmp);
    cudaGetSymbolAddress((void**)&attn, g_attn);
    cudaGetSymbolAddress((void**)&qkv,  g_qkv);
    cudaGetSymbolAddress((void**)&sc,   g_sc);
    cudaGetSymbolAddress((void**)&ff,   g_ff);
    cudaGetSymbolAddress((void**)&wt,   g_wt);
    cudaGetSymbolAddress((void**)&mu,   g_mu);
    cudaGetSymbolAddress((void**)&rstd, g_rstd);

    const long long HW  = (long long)Dm_ * Dk_;       // per-head weight block
    const long long QB  = (long long)Ss_ * 1536;      // per-batch stride in qkv
    const long long SCZ = (long long)Ss_ * Ss_;
    const float     isq = 0.125f;

    embed_kernel<<<BS_ * Dm_ / 256, 256>>>(tok, emb, x);

    for (int i = 0; i < Nx_; i++) {
        const float* wo1 = Wo1 + (long long)i * Dm_ * Dm_;
        const float* wo2 = Wo2 + (long long)i * Dm_ * Dm_;
        const float* w1  = W1  + (long long)i * Dm_ * Ff_;
        const float* w2  = W2  + (long long)i * Ff_ * Dm_;
        const float* bb1 = b1  + (long long)i * Ff_;
        const float* bb2 = b2  + (long long)i * Dm_;

        for (int attn_pass = 0; attn_pass < 2; attn_pass++) {
            const int self = (attn_pass == 0);
            if (self)
                pack_qkv_kernel<<<Dm_*1536/256, 256>>>(Wq1 + (long long)i*Hh_*HW,
                                                       Wk1 + (long long)i*Hh_*HW,
                                                       Wv1 + (long long)i*Hh_*HW, wt);
            else
                pack_qkv_kernel<<<Dm_*1536/256, 256>>>(Wq2 + (long long)i*Hh_*HW,
                                                       Wk2 + (long long)i*Hh_*HW,
                                                       Wv2 + (long long)i*Hh_*HW, wt);

            if (self) {
                gemm(x, wt, qkv, nullptr, nullptr, BS_, 1536, Dm_, Dm_, 1536, 1536,
                     0,0,1, 0,0,1, 0,0,1, 1, 1.f, 0, 0);
            } else {
                gemm(x, wt, qkv, nullptr, nullptr, BS_, 512, Dm_, Dm_, 1536, 1536,
                     0,0,1, 0,0,1, 0,0,1, 1, 1.f, 0, 0);
                gemm(enc, wt + 512, qkv + 512, nullptr, nullptr, BS_, 1024, Dm_, Dm_, 1536, 1536,
                     0,0,1, 0,0,1, 0,0,1, 1, 1.f, 0, 0);
            }
            // scores[z=b*8+h] = Q @ K^T * isq
            gemm(qkv, qkv + 512, sc, nullptr, nullptr, Ss_, Ss_, Dk_, 1536, 1536, Ss_,
                 QB, 64, Hh_,  QB, 64, Hh_,  SCZ, 0, 1,  Bb_*Hh_, isq, 1, 0);
            softmax_kernel<<<Bb_*Hh_*Ss_, 256, 256*4>>>(sc, Ss_, self ? 1 : 0);
            // attn[b,s,h*64+e] = probs @ V
            gemm(sc, qkv + 1024, attn, nullptr, nullptr, Ss_, Dk_, Ss_, Ss_, 1536, Dm_,
                 SCZ, 0, 1,  QB, 64, Hh_,  (long long)Ss_*Dm_, Dk_, Hh_,
                 Bb_*Hh_, 1.f, 0, 0);
            // tmp = attn @ Wo + x
            gemm(attn, self ? wo1 : wo2, tmp, nullptr, x, BS_, Dm_, Dm_, Dm_, Dm_, Dm_,
                 0,0,1, 0,0,1, 0,0,1, 1, 1.f, 0, 0);
            bn_stats_kernel<<<Dm_/32, dim3(32, 8)>>>(tmp, mu, rstd);
            bn_apply_kernel<<<BS_*Dm_/256, 256>>>(tmp, x, mu, rstd,
                                                  gamma + (long long)(i*3 + attn_pass)*Dm_,
                                                  beta  + (long long)(i*3 + attn_pass)*Dm_);
        }

        // ---- feed-forward
        gemm(x, w1, ff, bb1, nullptr, BS_, Ff_, Dm_, Dm_, Ff_, Ff_,
             0,0,1, 0,0,1, 0,0,1, 1, 1.f, 0, 1);
        gemm(ff, w2, tmp, bb2, x, BS_, Dm_, Ff_, Ff_, Dm_, Dm_,
             0,0,1, 0,0,1, 0,0,1, 1, 1.f, 0, 0);
        bn_stats_kernel<<<Dm_/32, dim3(32, 8)>>>(tmp, mu, rstd);
        bn_apply_kernel<<<BS_*Dm_/256, 256>>>(tmp, x, mu, rstd,
                                              gamma + (long long)(i*3 + 2)*Dm_,
                                              beta  + (long long)(i*3 + 2)*Dm_);
    }

    // ---- output projection + vocab softmax
    gemm(x, Wout, out, bout, nullptr, BS_, Vv_, Dm_, Dm_, Vv_, Vv_,
         0,0,1, 0,0,1, 0,0,1, 1, 1.f, 0, 0);
    softmax_kernel<<<BS_, 1024, 1024*4>>>(out, Vv_, 0);

    (void)in_sizes; (void)n_in; (void)out_size;
}

// round 4
// speedup vs baseline: 3.1576x; 1.5206x over previous
#include <cuda_runtime.h>
#include <cuda_fp16.h>
#include <math.h>
#include <stdint.h>

// ---------------------------------------------------------------------------
// Decoder — Round 4: 3xFP16 split GEMM (m16n8k16) + online softmax
// ---------------------------------------------------------------------------

#define Bb_ 4
#define Ss_ 512
#define Dm_ 512
#define Hh_ 8
#define Dk_ 64
#define Ff_ 2048
#define Vv_ 37000
#define Nx_ 6
#define BS_ 2048

// ------------------------- scratch (static device globals) -----------------
__device__ float g_x    [BS_*Dm_];
__device__ float g_tmp  [BS_*Dm_];
__device__ float g_attn [BS_*Dm_];
__device__ float g_qkv  [BS_*3*Dm_];           // [2048][1536]: Q|K|V (h-blocked)
__device__ float g_sc   [Bb_*Hh_*Ss_*Ss_];
__device__ float g_ff   [BS_*Ff_];
__device__ float g_wt   [Dm_*3*Dm_];           // packed QKV weights [512,1536]
__device__ float g_mu   [Dm_];
__device__ float g_rstd [Dm_];

// ------------------------------- helpers -----------------------------------
// fp32 -> (fp16 hi, fp16 lo) split of a float2 pair, packed as half2 regs.
__device__ __forceinline__ void split2(float2 x, uint32_t& hi, uint32_t& lo) {
    __half2 h = __float22half2_rn(x);
    float2 hf = __half22float2(h);
    __half2 l = __float22half2_rn(make_float2(x.x - hf.x, x.y - hf.y));
    hi = *reinterpret_cast<uint32_t*>(&h);
    lo = *reinterpret_cast<uint32_t*>(&l);
}

__device__ __forceinline__ void cpasync16(uint32_t dst, const void* src, int srcsize) {
    asm volatile("cp.async.cg.shared.global [%0], [%1], 16, %2;"
                 :: "r"(dst), "l"(src), "r"(srcsize));
}
__device__ __forceinline__ void cpcommit() { asm volatile("cp.async.commit_group;"); }
template <int NN> __device__ __forceinline__ void cpwait() {
    asm volatile("cp.async.wait_group %0;" :: "n"(NN));
}

__device__ __forceinline__ void mma16(float* d, const uint32_t* a, const uint32_t* b) {
    asm volatile(
        "mma.sync.aligned.m16n8k16.row.col.f32.f16.f16.f32 "
        "{%0,%1,%2,%3}, {%4,%5,%6,%7}, {%8,%9}, {%0,%1,%2,%3};"
        : "+f"(d[0]), "+f"(d[1]), "+f"(d[2]), "+f"(d[3])
        : "r"(a[0]), "r"(a[1]), "r"(a[2]), "r"(a[3]), "r"(b[0]), "r"(b[1]));
}

// ------------------------------ GEMM (3xFP16) -------------------------------
// C[z] = alpha * A[z] @ B[z](^T) (+bias)(+res)(relu)
// fp32-accurate: per-fragment hi/lo fp16 split, 3 MMAs per fragment pair.
// Tiles: BM=128, BN=128, BK=32. 256 threads = 8 warps (4 M x 2 N).
// flags: bit0 = relu.
#define ASTR 40
#define BSTRN 132
#define ASZ (128*ASTR)            // 5120 floats
#define BSZn (32*BSTRN)           // 4224 floats
#define BSZt (128*ASTR)           // 5120 floats
#define GEMM_SMEM_T ((2*ASZ + 2*BSZt)*4)   // 81920 B
#define GEMM_SMEM_N ((2*ASZ + 2*BSZn)*4)   // 74752 B

template <int TRANSB>
__global__ __launch_bounds__(256) void gemm_tc(
    const float* __restrict__ A, const float* __restrict__ B,
    float* __restrict__ C, const float* __restrict__ bias,
    const float* __restrict__ res,
    int M, int N, int K, int lda, int ldb, int ldc,
    long long aS1, long long aS2, int aDiv,
    long long bS1, long long bS2, int bDiv,
    long long cS1, long long cS2, int cDiv,
    float alpha, int flags)
{
    extern __shared__ float sm[];
    const int z = blockIdx.z;
    const float* Ab  = A + (long long)(z / aDiv) * aS1 + (long long)(z % aDiv) * aS2;
    const float* Bbp = B + (long long)(z / bDiv) * bS1 + (long long)(z % bDiv) * bS2;
    float*       Cb  = C + (long long)(z / cDiv) * cS1 + (long long)(z % cDiv) * cS2;

    const int BSZ = TRANSB ? BSZt : BSZn;
    float* As = sm;
    float* Bs = sm + 2 * ASZ;

    const int tid  = threadIdx.x;
    const int wid  = tid >> 5, lane = tid & 31;
    const int wm   = wid & 3,  wn   = wid >> 2;
    const int g    = lane >> 2, t   = lane & 3;
    const int m0   = blockIdx.y * 128, n0 = blockIdx.x * 128;

    const uint32_t asA = (uint32_t)__cvta_generic_to_shared(As);
    const uint32_t asB = (uint32_t)__cvta_generic_to_shared(Bs);

    float acc[2][8][4];
#pragma unroll
    for (int i = 0; i < 2; i++)
#pragma unroll
        for (int j = 0; j < 8; j++)
#pragma unroll
            for (int r = 0; r < 4; r++) acc[i][j][r] = 0.f;

    const int nIter = K >> 5;

    auto doCopy = [&](int it, int buf) {
        const int k0 = it << 5;
#pragma unroll
        for (int j = 0; j < 4; j++) {
            int i   = tid + (j << 8);
            int row = i >> 3, kq = (i & 7) << 2;
            const float* src = Ab + (long long)(m0 + row) * lda + (k0 + kq);
            cpasync16(asA + (uint32_t)((buf * ASZ + row * ASTR + kq) << 2), src, 16);
        }
        if (TRANSB) {
#pragma unroll
            for (int j = 0; j < 4; j++) {
                int i   = tid + (j << 8);
                int row = i >> 3, kq = (i & 7) << 2;
                int gn  = n0 + row;
                int sz  = (gn < N) ? 16 : 0;
                const float* src = Bbp + (long long)(sz ? gn : 0) * ldb + (k0 + kq);
                cpasync16(asB + (uint32_t)((buf * BSZ + row * ASTR + kq) << 2), src, sz);
            }
        } else {
#pragma unroll
            for (int j = 0; j < 4; j++) {
                int i  = tid + (j << 8);
                int kr = i >> 5, nc = (i & 31) << 2;
                int gn = n0 + nc;
                int sz = (gn < N) ? 16 : 0;
                const float* src = Bbp + (long long)(k0 + kr) * ldb + (sz ? gn : 0);
                cpasync16(asB + (uint32_t)((buf * BSZ + kr * BSTRN + nc) << 2), src, sz);
            }
        }
    };

    doCopy(0, 0); cpcommit();

    for (int it = 0; it < nIter; ++it) {
        const int cur = it & 1;
        if (it + 1 < nIter) { doCopy(it + 1, cur ^ 1); cpcommit(); cpwait<1>(); }
        else                { cpwait<0>(); }
        __syncthreads();

        const float* pa = As + cur * ASZ;
        const float* pb = Bs + cur * BSZ;

#pragma unroll
        for (int kk = 0; kk < 32; kk += 16) {
            // --- A fragments (m16n8k16 row-major): pairs at cols 2t,2t+1 (+8)
            uint32_t ah[2][4], al[2][4];
#pragma unroll
            for (int mt = 0; mt < 2; mt++) {
                int r0 = (wm * 32 + mt * 16 + g) * ASTR + kk + 2 * t;
                int r1 = r0 + 8 * ASTR;
                split2(*(const float2*)&pa[r0],     ah[mt][0], al[mt][0]);
                split2(*(const float2*)&pa[r1],     ah[mt][1], al[mt][1]);
                split2(*(const float2*)&pa[r0 + 8], ah[mt][2], al[mt][2]);
                split2(*(const float2*)&pa[r1 + 8], ah[mt][3], al[mt][3]);
            }
            // --- B fragments (col-major k x n): k pairs 2t,2t+1 (+8), col g
            uint32_t bh[8][2], bl[8][2];
#pragma unroll
            for (int nt = 0; nt < 8; nt++) {
                int nc = wn * 64 + nt * 8 + g;
                float2 y0, y1;
                if (TRANSB) {
                    y0 = *(const float2*)&pb[nc * ASTR + kk + 2 * t];
                    y1 = *(const float2*)&pb[nc * ASTR + kk + 2 * t + 8];
                } else {
                    const float* base = pb + (long long)(kk + 2 * t) * BSTRN + nc;
                    y0 = make_float2(base[0], base[BSTRN]);
                    y1 = make_float2(base[8 * BSTRN], base[9 * BSTRN]);
                }
                split2(y0, bh[nt][0], bl[nt][0]);
                split2(y1, bh[nt][1], bl[nt][1]);
            }
#pragma unroll
            for (int mt = 0; mt < 2; mt++)
#pragma unroll
                for (int nt = 0; nt < 8; nt++) {
                    mma16(acc[mt][nt], ah[mt], bh[nt]);   // hi*hi
                    mma16(acc[mt][nt], al[mt], bh[nt]);   // lo*hi
                    mma16(acc[mt][nt], ah[mt], bl[nt]);   // hi*lo
                }
        }
        __syncthreads();
    }

    // ------------------------------ epilogue --------------------------------
    const bool relu = flags & 1;
#pragma unroll
    for (int mt = 0; mt < 2; mt++) {
#pragma unroll
        for (int hrow = 0; hrow < 2; hrow++) {
            int m = m0 + wm * 32 + mt * 16 + g + hrow * 8;
#pragma unroll
            for (int nt = 0; nt < 8; nt++) {
                int n = n0 + wn * 64 + nt * 8 + 2 * t;
                if (n < N) {
                    float v0 = acc[mt][nt][hrow * 2 + 0] * alpha;
                    float v1 = acc[mt][nt][hrow * 2 + 1] * alpha;
                    if (bias) { v0 += bias[n]; v1 += bias[n + 1]; }
                    if (res) {
                        const float* rp = res + (long long)m * ldc;
                        v0 += rp[n]; v1 += rp[n + 1];
                    }
                    if (relu) { v0 = fmaxf(v0, 0.f); v1 = fmaxf(v1, 0.f); }
                    float2 vv; vv.x = v0; vv.y = v1;
                    *(float2*)(Cb + (long long)m * ldc + n) = vv;
                }
            }
        }
    }
}

// --------------------------- elementwise kernels ---------------------------
// Pack per-layer Wq/Wk/Wv ([H,D,dk] each) into [D, 1536] (Q|K|V, h-blocked).
__global__ void pack_qkv_kernel(const float* __restrict__ Wq, const float* __restrict__ Wk,
                                const float* __restrict__ Wv, float* __restrict__ wt) {
    int idx = blockIdx.x * 256 + threadIdx.x;        // < 512*1536
    int col = idx % 1536, d = idx / 1536;
    int sel = col >> 9, c = col & 511;
    int h = c >> 6, e = c & 63;
    const float* W = (sel == 0) ? Wq : (sel == 1) ? Wk : Wv;
    wt[idx] = W[(h * Dm_ + d) * Dk_ + e];
}

__global__ void embed_kernel(const int* __restrict__ tok, const float* __restrict__ emb,
                             float* __restrict__ x) {
    int idx = blockIdx.x * 256 + threadIdx.x;        // < 2048*512
    int t = tok[idx >> 9];
    x[idx] = emb[(long long)t * Dm_ + (idx & 511)] * 8.0f;
}

__global__ void bn_stats_kernel(const float* __restrict__ x,
                                float* __restrict__ mu, float* __restrict__ rstd) {
    int d = blockIdx.x * 32 + threadIdx.x;
    float s = 0.f, s2 = 0.f;
    for (int i = threadIdx.y; i < BS_; i += 8) {
        float v = x[(long long)i * Dm_ + d];
        s += v; s2 += v * v;
    }
    __shared__ float sh[8][33], sh2[8][33];
    sh[threadIdx.y][threadIdx.x] = s;
    sh2[threadIdx.y][threadIdx.x] = s2;
    __syncthreads();
    if (threadIdx.y == 0) {
#pragma unroll
        for (int r = 1; r < 8; r++) { s += sh[r][threadIdx.x]; s2 += sh2[r][threadIdx.x]; }
        float m = s * (1.f / BS_);
        float var = s2 * (1.f / BS_) - m * m;
        mu[d] = m;
        rstd[d] = rsqrtf(var + 1e-5f);
    }
}

__global__ void bn_apply_kernel(const float* __restrict__ xin, float* __restrict__ xout,
                                const float* __restrict__ mu, const float* __restrict__ rstd,
                                const float* __restrict__ gamma, const float* __restrict__ beta) {
    int idx = blockIdx.x * 256 + threadIdx.x;
    int d = idx & 511;
    xout[idx] = (xin[idx] - mu[d]) * rstd[d] * gamma[d] + beta[d];
}

// Online row softmax (2 reads + 1 write). Causal masks t > (row & 511).
__global__ void softmax_kernel(float* __restrict__ p, int T, int causal) {
    extern __shared__ float red[];          // [2 * blockDim.x]
    float* mred = red;
    float* sred = red + blockDim.x;
    long long row = blockIdx.x;
    float* x = p + row * (long long)T;
    int s = (int)(row & 511);
    int nt = blockDim.x;
    int tmax = causal ? s : (T - 1);

    float m = -1e30f, sum = 0.f;
    for (int t = threadIdx.x; t <= tmax; t += nt) {
        float v = x[t];
        if (v > m) { sum = sum * __expf(m - v) + 1.f; m = v; }
        else       { sum += __expf(v - m); }
    }
    mred[threadIdx.x] = m; sred[threadIdx.x] = sum;
    __syncthreads();
    for (int o = nt >> 1; o > 0; o >>= 1) {
        if ((int)threadIdx.x < o) {
            float m2 = mred[threadIdx.x + o], s2 = sred[threadIdx.x + o];
            float m1 = mred[threadIdx.x],     s1 = sred[threadIdx.x];
            float M = fmaxf(m1, m2);
            sred[threadIdx.x] = s1 * __expf(m1 - M) + s2 * __expf(m2 - M);
            mred[threadIdx.x] = M;
        }
        __syncthreads();
    }
    float M = mred[0];
    float inv = 1.f / sred[0];
    for (int t = threadIdx.x; t < T; t += nt) {
        float v = (causal && t > s) ? 0.f : __expf(x[t] - M) * inv;
        x[t] = v;
    }
}

// ------------------------------- host side ---------------------------------
static inline int cdiv(int a, int b) { return (a + b - 1) / b; }

static void gemm(const float* A, const float* B, float* C,
                 const float* bias, const float* res,
                 int M, int N, int K, int lda, int ldb, int ldc,
                 long long aS1, long long aS2, int aDiv,
                 long long bS1, long long bS2, int bDiv,
                 long long cS1, long long cS2, int cDiv,
                 int batch, float alpha, int transB, int flags)
{
    dim3 grd(cdiv(N, 128), M / 128, batch);
    if (transB)
        gemm_tc<1><<<grd, 256, GEMM_SMEM_T>>>(A, B, C, bias, res, M, N, K, lda, ldb, ldc,
                                              aS1, aS2, aDiv, bS1, bS2, bDiv, cS1, cS2, cDiv,
                                              alpha, flags);
    else
        gemm_tc<0><<<grd, 256, GEMM_SMEM_N>>>(A, B, C, bias, res, M, N, K, lda, ldb, ldc,
                                              aS1, aS2, aDiv, bS1, bS2, bDiv, cS1, cS2, cDiv,
                                              alpha, flags);
}

extern "C" void kernel_launch(void* const* d_in, const int* in_sizes, int n_in,
                              void* d_out, int out_size)
{
    const int*   tok   = (const int*)  d_in[0];
    const float* enc   = (const float*)d_in[1];
    const float* emb   = (const float*)d_in[2];
    const float* Wq1   = (const float*)d_in[3];
    const float* Wk1   = (const float*)d_in[4];
    const float* Wv1   = (const float*)d_in[5];
    const float* Wo1   = (const float*)d_in[6];
    const float* Wq2   = (const float*)d_in[7];
    const float* Wk2   = (const float*)d_in[8];
    const float* Wv2   = (const float*)d_in[9];
    const float* Wo2   = (const float*)d_in[10];
    const float* gamma = (const float*)d_in[11];
    const float* beta  = (const float*)d_in[12];
    const float* W1    = (const float*)d_in[13];
    const float* b1    = (const float*)d_in[14];
    const float* W2    = (const float*)d_in[15];
    const float* b2    = (const float*)d_in[16];
    const float* Wout  = (const float*)d_in[17];
    const float* bout  = (const float*)d_in[18];
    float* out = (float*)d_out;

    cudaFuncSetAttribute(gemm_tc<0>, cudaFuncAttributeMaxDynamicSharedMemorySize, GEMM_SMEM_N);
    cudaFuncSetAttribute(gemm_tc<1>, cudaFuncAttributeMaxDynamicSharedMemorySize, GEMM_SMEM_T);

    float *x, *tmp, *attn, *qkv, *sc, *ff, *wt, *mu, *rstd;
    cudaGetSymbolAddress((void**)&x,    g_x);
    cudaGetSymbolAddress((void**)&tmp,  g_tmp);
    cudaGetSymbolAddress((void**)&attn, g_attn);
    cudaGetSymbolAddress((void**)&qkv,  g_qkv);
    cudaGetSymbolAddress((void**)&sc,   g_sc);
    cudaGetSymbolAddress((void**)&ff,   g_ff);
    cudaGetSymbolAddress((void**)&wt,   g_wt);
    cudaGetSymbolAddress((void**)&mu,   g_mu);
    cudaGetSymbolAddress((void**)&rstd, g_rstd);

    const long long HW  = (long long)Dm_ * Dk_;       // per-head weight block
    const long long QB  = (long long)Ss_ * 1536;      // per-batch stride in qkv
    const long long SCZ = (long long)Ss_ * Ss_;
    const float     isq = 0.125f;

    embed_kernel<<<BS_ * Dm_ / 256, 256>>>(tok, emb, x);

    for (int i = 0; i < Nx_; i++) {
        const float* wo1 = Wo1 + (long long)i * Dm_ * Dm_;
        const float* wo2 = Wo2 + (long long)i * Dm_ * Dm_;
        const float* w1  = W1  + (long long)i * Dm_ * Ff_;
        const float* w2  = W2  + (long long)i * Ff_ * Dm_;
        const float* bb1 = b1  + (long long)i * Ff_;
        const float* bb2 = b2  + (long long)i * Dm_;

        for (int attn_pass = 0; attn_pass < 2; attn_pass++) {
            const int self = (attn_pass == 0);
            if (self)
                pack_qkv_kernel<<<Dm_*1536/256, 256>>>(Wq1 + (long long)i*Hh_*HW,
                                                       Wk1 + (long long)i*Hh_*HW,
                                                       Wv1 + (long long)i*Hh_*HW, wt);
            else
                pack_qkv_kernel<<<Dm_*1536/256, 256>>>(Wq2 + (long long)i*Hh_*HW,
                                                       Wk2 + (long long)i*Hh_*HW,
                                                       Wv2 + (long long)i*Hh_*HW, wt);

            if (self) {
                gemm(x, wt, qkv, nullptr, nullptr, BS_, 1536, Dm_, Dm_, 1536, 1536,
                     0,0,1, 0,0,1, 0,0,1, 1, 1.f, 0, 0);
            } else {
                gemm(x, wt, qkv, nullptr, nullptr, BS_, 512, Dm_, Dm_, 1536, 1536,
                     0,0,1, 0,0,1, 0,0,1, 1, 1.f, 0, 0);
                gemm(enc, wt + 512, qkv + 512, nullptr, nullptr, BS_, 1024, Dm_, Dm_, 1536, 1536,
                     0,0,1, 0,0,1, 0,0,1, 1, 1.f, 0, 0);
            }
            // scores[z=b*8+h] = Q @ K^T * isq
            gemm(qkv, qkv + 512, sc, nullptr, nullptr, Ss_, Ss_, Dk_, 1536, 1536, Ss_,
                 QB, 64, Hh_,  QB, 64, Hh_,  SCZ, 0, 1,  Bb_*Hh_, isq, 1, 0);
            softmax_kernel<<<Bb_*Hh_*Ss_, 256, 2*256*4>>>(sc, Ss_, self ? 1 : 0);
            // attn[b,s,h*64+e] = probs @ V
            gemm(sc, qkv + 1024, attn, nullptr, nullptr, Ss_, Dk_, Ss_, Ss_, 1536, Dm_,
                 SCZ, 0, 1,  QB, 64, Hh_,  (long long)Ss_*Dm_, Dk_, Hh_,
                 Bb_*Hh_, 1.f, 0, 0);
            // tmp = attn @ Wo + x
            gemm(attn, self ? wo1 : wo2, tmp, nullptr, x, BS_, Dm_, Dm_, Dm_, Dm_, Dm_,
                 0,0,1, 0,0,1, 0,0,1, 1, 1.f, 0, 0);
            bn_stats_kernel<<<Dm_/32, dim3(32, 8)>>>(tmp, mu, rstd);
            bn_apply_kernel<<<BS_*Dm_/256, 256>>>(tmp, x, mu, rstd,
                                                  gamma + (long long)(i*3 + attn_pass)*Dm_,
                                                  beta  + (long long)(i*3 + attn_pass)*Dm_);
        }

        // ---- feed-forward
        gemm(x, w1, ff, bb1, nullptr, BS_, Ff_, Dm_, Dm_, Ff_, Ff_,
             0,0,1, 0,0,1, 0,0,1, 1, 1.f, 0, 1);
        gemm(ff, w2, tmp, bb2, x, BS_, Dm_, Ff_, Ff_, Dm_, Dm_,
             0,0,1, 0,0,1, 0,0,1, 1, 1.f, 0, 0);
        bn_stats_kernel<<<Dm_/32, dim3(32, 8)>>>(tmp, mu, rstd);
        bn_apply_kernel<<<BS_*Dm_/256, 256>>>(tmp, x, mu, rstd,
                                              gamma + (long long)(i*3 + 2)*Dm_,
                                              beta  + (long long)(i*3 + 2)*Dm_);
    }

    // ---- output projection + vocab softmax
    gemm(x, Wout, out, bout, nullptr, BS_, Vv_, Dm_, Dm_, Vv_, Vv_,
         0,0,1, 0,0,1, 0,0,1, 1, 1.f, 0, 0);
    softmax_kernel<<<BS_, 1024, 2*1024*4>>>(out, Vv_, 0);

    (void)in_sizes; (void)n_in; (void)out_size;
}